// round 3
// baseline (speedup 1.0000x reference)
#include <cuda_runtime.h>
#include <cuda_bf16.h>

#define N_NODES 50000
#define N_EDGES 600000
#define DIMH    128
#define NLAYER  3
#define NCLS    40
#define LN_EPS  1e-5f

// ---------------- scratch (static device globals; no allocations) ------------
__device__ float g_deg [N_NODES];
__device__ float g_dinv[N_NODES];
__device__ float g_x   [N_NODES * DIMH];  // current layer input
__device__ float g_h   [N_NODES * DIMH];  // h * dinv[row]  (pre-scaled)
__device__ float g_acc [N_NODES * DIMH];  // aggregation accumulator
__device__ float g_fin [N_NODES * DIMH];  // JK sum

// ---------------- init: copy x in, zero JK sum + degree ----------------------
__global__ void init_kernel(const float* __restrict__ x) {
    int i = blockIdx.x * blockDim.x + threadIdx.x;
    if (i < N_NODES * DIMH) { g_x[i] = x[i]; g_fin[i] = 0.f; }
    if (i < N_NODES) g_deg[i] = 0.f;
}

__global__ void deg_kernel(const int* __restrict__ ei) {
    int e = blockIdx.x * blockDim.x + threadIdx.x;
    if (e < N_EDGES) atomicAdd(&g_deg[ei[N_EDGES + e]], 1.0f);
}

__global__ void dinv_kernel() {
    int i = blockIdx.x * blockDim.x + threadIdx.x;
    if (i < N_NODES) g_dinv[i] = rsqrtf(g_deg[i] + 1.0f);
}

// ---------------- fused dual GEMM ---------------------------------------------
// h_scaled = (x@Wc) * dinv ;  acc = h_scaled*dinv + bc + x@Wl + bl
// 64 rows per block, 256 threads. k-chunked (32) smem tiles for x and both W.
// Thread (tx,ty): 8-row x 4-col microtile for each of the two outputs.
// LDS patterns: xs row read is a per-warp broadcast (ty == warp id);
// float4 weight reads are 4-phase conflict-free.
__global__ __launch_bounds__(256) void gemm_dual_kernel(
    const float* __restrict__ Wc, const float* __restrict__ bcv,
    const float* __restrict__ Wl, const float* __restrict__ blv) {
    __shared__ float xs [64][33];     // [row][k], padded
    __shared__ float wsC[32][128];    // [k][h]
    __shared__ float wsL[32][128];

    const int tid = threadIdx.x;
    const int tx  = tid & 31;         // 0..31 -> 4 cols each
    const int ty  = tid >> 5;         // 0..7  -> 8 rows each
    const int row0 = blockIdx.x * 64;

    float accC[8][4] = {{0.f}};
    float accL[8][4] = {{0.f}};

    for (int k0 = 0; k0 < DIMH; k0 += 32) {
        // load x tile (64 rows x 32 k), coalesced over k
        {
            const int kk = tid & 31;
            const int rb = tid >> 5;
#pragma unroll
            for (int rr = 0; rr < 8; rr++) {
                int r = rb + rr * 8;
                int row = row0 + r;
                xs[r][kk] = (row < N_NODES) ? __ldg(&g_x[row * DIMH + k0 + kk]) : 0.f;
            }
        }
        // load both weight k-chunks (32 x 128 each), coalesced over h
#pragma unroll
        for (int it = 0; it < 16; it++) {
            int j = tid + it * 256;
            int kk = j >> 7, h = j & 127;
            wsC[kk][h] = __ldg(&Wc[(k0 + kk) * DIMH + h]);
            wsL[kk][h] = __ldg(&Wl[(k0 + kk) * DIMH + h]);
        }
        __syncthreads();

#pragma unroll
        for (int kk = 0; kk < 32; kk++) {
            float a[8];
#pragma unroll
            for (int r = 0; r < 8; r++) a[r] = xs[ty * 8 + r][kk];   // broadcast
            const float4 bC = ((const float4*)wsC[kk])[tx];          // LDS.128
            const float4 bL = ((const float4*)wsL[kk])[tx];
            const float bCv[4] = {bC.x, bC.y, bC.z, bC.w};
            const float bLv[4] = {bL.x, bL.y, bL.z, bL.w};
#pragma unroll
            for (int r = 0; r < 8; r++)
#pragma unroll
                for (int c = 0; c < 4; c++) {
                    accC[r][c] = fmaf(a[r], bCv[c], accC[r][c]);
                    accL[r][c] = fmaf(a[r], bLv[c], accL[r][c]);
                }
        }
        __syncthreads();
    }

    // epilogue: write h*dinv, and acc = (h*dinv)*dinv + bconv + xlin + blin
#pragma unroll
    for (int r = 0; r < 8; r++) {
        int row = row0 + ty * 8 + r;
        if (row >= N_NODES) continue;
        float dv = g_dinv[row];
#pragma unroll
        for (int c = 0; c < 4; c++) {
            int col = tx * 4 + c;
            float hs = accC[r][c] * dv;                 // h * dinv[src-side]
            g_h  [row * DIMH + col] = hs;
            g_acc[row * DIMH + col] = fmaf(hs, dv, bcv[col]) + accL[r][c] + blv[col];
        }
    }
}

// ---------------- edge scatter: acc[dst] += dinv[dst] * h_scaled[src] --------
// one warp per edge; float4 gather, ONE red.global.add.v4.f32 per lane
__global__ __launch_bounds__(256) void scatter_kernel(const int* __restrict__ ei) {
    int e = blockIdx.x * 8 + (threadIdx.x >> 5);
    int lane = threadIdx.x & 31;
    if (e >= N_EDGES) return;
    int src = __ldg(&ei[e]);
    int dst = __ldg(&ei[N_EDGES + e]);
    float w = __ldg(&g_dinv[dst]);
    float4 v = __ldg((const float4*)(g_h + (size_t)src * DIMH) + lane);
    float* arow = g_acc + (size_t)dst * DIMH + lane * 4;
    asm volatile(
        "red.global.add.v4.f32 [%0], {%1, %2, %3, %4};"
        :: "l"(arow), "f"(v.x * w), "f"(v.y * w), "f"(v.z * w), "f"(v.w * w)
        : "memory");
}

// ---------------- LayerNorm + ReLU + JK accumulate, warp per row -------------
__global__ __launch_bounds__(256) void ln_kernel(const float* __restrict__ gam,
                                                 const float* __restrict__ bet) {
    int row = blockIdx.x * 8 + (threadIdx.x >> 5);
    int lane = threadIdx.x & 31;
    if (row >= N_NODES) return;
    float4 v = ((const float4*)(g_acc + (size_t)row * DIMH))[lane];
    float s  = v.x + v.y + v.z + v.w;
    float sq = v.x * v.x + v.y * v.y + v.z * v.z + v.w * v.w;
#pragma unroll
    for (int o = 16; o; o >>= 1) {
        s  += __shfl_xor_sync(0xFFFFFFFFu, s,  o);
        sq += __shfl_xor_sync(0xFFFFFFFFu, sq, o);
    }
    const float inv128 = 1.0f / 128.0f;
    float mu  = s * inv128;
    float var = sq * inv128 - mu * mu;
    float istd = rsqrtf(var + LN_EPS);
    float4 gg = __ldg((const float4*)gam + lane);
    float4 bb = __ldg((const float4*)bet + lane);
    float4 y;
    y.x = fmaxf((v.x - mu) * istd * gg.x + bb.x, 0.f);
    y.y = fmaxf((v.y - mu) * istd * gg.y + bb.y, 0.f);
    y.z = fmaxf((v.z - mu) * istd * gg.z + bb.z, 0.f);
    y.w = fmaxf((v.w - mu) * istd * gg.w + bb.w, 0.f);
    ((float4*)(g_x + (size_t)row * DIMH))[lane] = y;
    float4 f = ((const float4*)(g_fin + (size_t)row * DIMH))[lane];
    f.x += y.x; f.y += y.y; f.z += y.z; f.w += y.w;
    ((float4*)(g_fin + (size_t)row * DIMH))[lane] = f;
}

// ---------------- prediction head: out = fin @ Wpred + bpred -----------------
// 16 rows per block, 128 threads, Wpred + row tile in smem
__global__ __launch_bounds__(128) void pred_kernel(const float* __restrict__ Wp,
                                                   const float* __restrict__ bp,
                                                   float* __restrict__ out) {
    __shared__ float ws[DIMH * NCLS];   // 20 KB
    __shared__ float fs[16][DIMH];      // 8 KB
    int tid = threadIdx.x;
    for (int j = tid; j < DIMH * NCLS; j += 128) ws[j] = __ldg(&Wp[j]);
    int row0 = blockIdx.x * 16;
    for (int j = tid; j < 16 * DIMH; j += 128) {
        int r = j >> 7, k = j & 127;
        int row = row0 + r;
        fs[r][k] = (row < N_NODES) ? g_fin[row * DIMH + k] : 0.f;
    }
    __syncthreads();
    for (int idx = tid; idx < 16 * NCLS; idx += 128) {
        int r = idx / NCLS, c = idx % NCLS;
        int row = row0 + r;
        if (row >= N_NODES) continue;
        float acc = __ldg(&bp[c]);
#pragma unroll 8
        for (int k = 0; k < DIMH; k++) acc = fmaf(fs[r][k], ws[k * NCLS + c], acc);
        out[row * NCLS + c] = acc;
    }
}

// ---------------- launch ------------------------------------------------------
extern "C" void kernel_launch(void* const* d_in, const int* in_sizes, int n_in,
                              void* d_out, int out_size) {
    const float* x  = (const float*)d_in[0];
    const int*   ei = (const int*)  d_in[1];
    const float* Wc = (const float*)d_in[2];
    const float* bc = (const float*)d_in[3];
    const float* Wl = (const float*)d_in[4];
    const float* bl = (const float*)d_in[5];
    const float* lg = (const float*)d_in[6];
    const float* lb = (const float*)d_in[7];
    const float* Wp = (const float*)d_in[8];
    const float* bp = (const float*)d_in[9];
    float* out = (float*)d_out;

    init_kernel<<<(N_NODES * DIMH + 255) / 256, 256>>>(x);
    deg_kernel<<<(N_EDGES + 255) / 256, 256>>>(ei);
    dinv_kernel<<<(N_NODES + 255) / 256, 256>>>();

    for (int i = 0; i < NLAYER; i++) {
        gemm_dual_kernel<<<(N_NODES + 63) / 64, 256>>>(
            Wc + i * DIMH * DIMH, bc + i * DIMH,
            Wl + i * DIMH * DIMH, bl + i * DIMH);
        scatter_kernel<<<(N_EDGES + 7) / 8, 256>>>(ei);
        ln_kernel<<<(N_NODES + 7) / 8, 256>>>(lg + i * DIMH, lb + i * DIMH);
    }

    pred_kernel<<<(N_NODES + 15) / 16, 128>>>(Wp, bp, out);
}

// round 4
// speedup vs baseline: 1.0425x; 1.0425x over previous
#include <cuda_runtime.h>
#include <cuda_bf16.h>

#define N_NODES 50000
#define N_EDGES 600000
#define DIMH    128
#define NLAYER  3
#define NCLS    40
#define LN_EPS  1e-5f

// ---------------- scratch (static device globals; no allocations) ------------
__device__ float g_deg [N_NODES];
__device__ float g_dinv[N_NODES];
__device__ float g_x   [N_NODES * DIMH];  // current layer input
__device__ float g_h   [N_NODES * DIMH];  // h * dinv[row]  (pre-scaled)
__device__ float g_acc [N_NODES * DIMH];  // aggregation accumulator
__device__ float g_fin [N_NODES * DIMH];  // JK sum

// ---------------- init: copy x in, zero JK sum + degree ----------------------
__global__ void init_kernel(const float* __restrict__ x) {
    int i = blockIdx.x * blockDim.x + threadIdx.x;
    if (i < N_NODES * DIMH) { g_x[i] = x[i]; g_fin[i] = 0.f; }
    if (i < N_NODES) g_deg[i] = 0.f;
}

__global__ void deg_kernel(const int* __restrict__ ei) {
    int e = blockIdx.x * blockDim.x + threadIdx.x;
    if (e < N_EDGES) atomicAdd(&g_deg[ei[N_EDGES + e]], 1.0f);
}

__global__ void dinv_kernel() {
    int i = blockIdx.x * blockDim.x + threadIdx.x;
    if (i < N_NODES) g_dinv[i] = rsqrtf(g_deg[i] + 1.0f);
}

// ---------------- fused dual GEMM ---------------------------------------------
// h_scaled = (x@Wc) * dinv ;  acc = h_scaled*dinv + bc + x@Wl + bl
// 64 rows per block, 256 threads, 2 CTAs/SM. k-chunked (32).
// x tile stored TRANSPOSED [k][row] (stride 68: 16B-aligned rows, odd-ish bank
// pattern -> 4-way conflict only on the store side). Inner loop per k-step:
//   2x LDS.128 (a, warp-broadcast) + 2x LDS.128 (b) + 64 FFMA.
__global__ __launch_bounds__(256, 2) void gemm_dual_kernel(
    const float* __restrict__ Wc, const float* __restrict__ bcv,
    const float* __restrict__ Wl, const float* __restrict__ blv) {
    __shared__ float xs_t[32][68];    // [k][row], stride 68 floats
    __shared__ float wsC [32][128];   // [k][h]
    __shared__ float wsL [32][128];

    const int tid = threadIdx.x;
    const int tx  = tid & 31;         // 0..31 -> 4 cols each
    const int ty  = tid >> 5;         // 0..7  -> 8 rows each
    const int row0 = blockIdx.x * 64;

    float accC[8][4] = {{0.f}};
    float accL[8][4] = {{0.f}};

    for (int k0 = 0; k0 < DIMH; k0 += 32) {
        // load x tile (64 rows x 32 k) transposed; gmem coalesced over kk
        {
            const int kk = tid & 31;
            const int rb = tid >> 5;
#pragma unroll
            for (int rr = 0; rr < 8; rr++) {
                int r = rb + rr * 8;
                int row = row0 + r;
                xs_t[kk][r] = (row < N_NODES) ? __ldg(&g_x[row * DIMH + k0 + kk]) : 0.f;
            }
        }
        // load both weight k-chunks (32 x 128 each), coalesced over h
#pragma unroll
        for (int it = 0; it < 16; it++) {
            int j = tid + it * 256;
            int kk = j >> 7, h = j & 127;
            wsC[kk][h] = __ldg(&Wc[(k0 + kk) * DIMH + h]);
            wsL[kk][h] = __ldg(&Wl[(k0 + kk) * DIMH + h]);
        }
        __syncthreads();

#pragma unroll
        for (int kk = 0; kk < 32; kk++) {
            const float4 a0 = *(const float4*)&xs_t[kk][ty * 8];      // broadcast
            const float4 a1 = *(const float4*)&xs_t[kk][ty * 8 + 4];  // broadcast
            const float av[8] = {a0.x, a0.y, a0.z, a0.w, a1.x, a1.y, a1.z, a1.w};
            const float4 bC = ((const float4*)wsC[kk])[tx];           // LDS.128
            const float4 bL = ((const float4*)wsL[kk])[tx];
            const float bCv[4] = {bC.x, bC.y, bC.z, bC.w};
            const float bLv[4] = {bL.x, bL.y, bL.z, bL.w};
#pragma unroll
            for (int r = 0; r < 8; r++)
#pragma unroll
                for (int c = 0; c < 4; c++) {
                    accC[r][c] = fmaf(av[r], bCv[c], accC[r][c]);
                    accL[r][c] = fmaf(av[r], bLv[c], accL[r][c]);
                }
        }
        __syncthreads();
    }

    // epilogue: write h*dinv, and acc = (h*dinv)*dinv + bconv + xlin + blin
#pragma unroll
    for (int r = 0; r < 8; r++) {
        int row = row0 + ty * 8 + r;
        if (row >= N_NODES) continue;
        float dv = g_dinv[row];
#pragma unroll
        for (int c = 0; c < 4; c++) {
            int col = tx * 4 + c;
            float hs = accC[r][c] * dv;                 // h * dinv[src-side]
            g_h  [row * DIMH + col] = hs;
            g_acc[row * DIMH + col] = fmaf(hs, dv, bcv[col]) + accL[r][c] + blv[col];
        }
    }
}

// ---------------- edge scatter: acc[dst] += dinv[dst] * h_scaled[src] --------
// one warp per edge; float4 gather, ONE red.global.add.v4.f32 per lane
__global__ __launch_bounds__(256) void scatter_kernel(const int* __restrict__ ei) {
    int e = blockIdx.x * 8 + (threadIdx.x >> 5);
    int lane = threadIdx.x & 31;
    if (e >= N_EDGES) return;
    int src = __ldg(&ei[e]);
    int dst = __ldg(&ei[N_EDGES + e]);
    float w = __ldg(&g_dinv[dst]);
    float4 v = __ldg((const float4*)(g_h + (size_t)src * DIMH) + lane);
    float* arow = g_acc + (size_t)dst * DIMH + lane * 4;
    asm volatile(
        "red.global.add.v4.f32 [%0], {%1, %2, %3, %4};"
        :: "l"(arow), "f"(v.x * w), "f"(v.y * w), "f"(v.z * w), "f"(v.w * w)
        : "memory");
}

// ---------------- LayerNorm + ReLU + JK accumulate, warp per row -------------
__global__ __launch_bounds__(256) void ln_kernel(const float* __restrict__ gam,
                                                 const float* __restrict__ bet) {
    int row = blockIdx.x * 8 + (threadIdx.x >> 5);
    int lane = threadIdx.x & 31;
    if (row >= N_NODES) return;
    float4 v = ((const float4*)(g_acc + (size_t)row * DIMH))[lane];
    float s  = v.x + v.y + v.z + v.w;
    float sq = v.x * v.x + v.y * v.y + v.z * v.z + v.w * v.w;
#pragma unroll
    for (int o = 16; o; o >>= 1) {
        s  += __shfl_xor_sync(0xFFFFFFFFu, s,  o);
        sq += __shfl_xor_sync(0xFFFFFFFFu, sq, o);
    }
    const float inv128 = 1.0f / 128.0f;
    float mu  = s * inv128;
    float var = sq * inv128 - mu * mu;
    float istd = rsqrtf(var + LN_EPS);
    float4 gg = __ldg((const float4*)gam + lane);
    float4 bb = __ldg((const float4*)bet + lane);
    float4 y;
    y.x = fmaxf((v.x - mu) * istd * gg.x + bb.x, 0.f);
    y.y = fmaxf((v.y - mu) * istd * gg.y + bb.y, 0.f);
    y.z = fmaxf((v.z - mu) * istd * gg.z + bb.z, 0.f);
    y.w = fmaxf((v.w - mu) * istd * gg.w + bb.w, 0.f);
    ((float4*)(g_x + (size_t)row * DIMH))[lane] = y;
    float4 f = ((const float4*)(g_fin + (size_t)row * DIMH))[lane];
    f.x += y.x; f.y += y.y; f.z += y.z; f.w += y.w;
    ((float4*)(g_fin + (size_t)row * DIMH))[lane] = f;
}

// ---------------- prediction head: out = fin @ Wpred + bpred -----------------
// 16 rows per block, 128 threads, Wpred + row tile in smem
__global__ __launch_bounds__(128) void pred_kernel(const float* __restrict__ Wp,
                                                   const float* __restrict__ bp,
                                                   float* __restrict__ out) {
    __shared__ float ws[DIMH * NCLS];   // 20 KB
    __shared__ float fs[16][DIMH];      // 8 KB
    int tid = threadIdx.x;
    for (int j = tid; j < DIMH * NCLS; j += 128) ws[j] = __ldg(&Wp[j]);
    int row0 = blockIdx.x * 16;
    for (int j = tid; j < 16 * DIMH; j += 128) {
        int r = j >> 7, k = j & 127;
        int row = row0 + r;
        fs[r][k] = (row < N_NODES) ? g_fin[row * DIMH + k] : 0.f;
    }
    __syncthreads();
    for (int idx = tid; idx < 16 * NCLS; idx += 128) {
        int r = idx / NCLS, c = idx % NCLS;
        int row = row0 + r;
        if (row >= N_NODES) continue;
        float acc = __ldg(&bp[c]);
#pragma unroll 8
        for (int k = 0; k < DIMH; k++) acc = fmaf(fs[r][k], ws[k * NCLS + c], acc);
        out[row * NCLS + c] = acc;
    }
}

// ---------------- launch ------------------------------------------------------
extern "C" void kernel_launch(void* const* d_in, const int* in_sizes, int n_in,
                              void* d_out, int out_size) {
    const float* x  = (const float*)d_in[0];
    const int*   ei = (const int*)  d_in[1];
    const float* Wc = (const float*)d_in[2];
    const float* bc = (const float*)d_in[3];
    const float* Wl = (const float*)d_in[4];
    const float* bl = (const float*)d_in[5];
    const float* lg = (const float*)d_in[6];
    const float* lb = (const float*)d_in[7];
    const float* Wp = (const float*)d_in[8];
    const float* bp = (const float*)d_in[9];
    float* out = (float*)d_out;

    init_kernel<<<(N_NODES * DIMH + 255) / 256, 256>>>(x);
    deg_kernel<<<(N_EDGES + 255) / 256, 256>>>(ei);
    dinv_kernel<<<(N_NODES + 255) / 256, 256>>>();

    for (int i = 0; i < NLAYER; i++) {
        gemm_dual_kernel<<<(N_NODES + 63) / 64, 256>>>(
            Wc + i * DIMH * DIMH, bc + i * DIMH,
            Wl + i * DIMH * DIMH, bl + i * DIMH);
        scatter_kernel<<<(N_EDGES + 7) / 8, 256>>>(ei);
        ln_kernel<<<(N_NODES + 7) / 8, 256>>>(lg + i * DIMH, lb + i * DIMH);
    }

    pred_kernel<<<(N_NODES + 15) / 16, 128>>>(Wp, bp, out);
}

// round 6
// speedup vs baseline: 1.1737x; 1.1259x over previous
#include <cuda_runtime.h>
#include <cuda_bf16.h>

#define N_NODES 50000
#define N_EDGES 600000
#define DIMH    128
#define NLAYER  3
#define NCLS    40
#define LN_EPS  1e-5f

// A-fragment region size in floats: [16 kt][4 mt][32 lane][4 slot]
#define AFRAG_FLOATS 8192

// ---------------- scratch (static device globals; no allocations) ------------
__device__ float g_deg [N_NODES];
__device__ float g_dinv[N_NODES];
__device__ __align__(16) float g_x   [N_NODES * DIMH];  // current layer input
__device__ __align__(16) float g_h   [N_NODES * DIMH];  // h * dinv[row]
__device__ __align__(16) float g_acc [N_NODES * DIMH];  // aggregation accumulator
__device__ __align__(16) float g_fin [N_NODES * DIMH];  // JK sum
// fragment-ordered tf32 hi/lo weights: 6 matrices (layer*2 + {conv,lin}),
// each 128x128 -> 16x16 tiles x 32 lanes x float4 {b0hi,b1hi,b0lo,b1lo}
#define WFRAG_MAT (DIMH * DIMH * 2)          // 32768 floats per matrix
__device__ __align__(16) float g_wfrag[NLAYER * 2 * WFRAG_MAT];

// ---------------- init: copy x in, zero JK sum + degree ----------------------
__global__ void init_kernel(const float* __restrict__ x) {
    int i = blockIdx.x * blockDim.x + threadIdx.x;
    if (i < N_NODES * DIMH) { g_x[i] = x[i]; g_fin[i] = 0.f; }
    if (i < N_NODES) g_deg[i] = 0.f;
}

__global__ void deg_kernel(const int* __restrict__ ei) {
    int e = blockIdx.x * blockDim.x + threadIdx.x;
    if (e < N_EDGES) atomicAdd(&g_deg[ei[N_EDGES + e]], 1.0f);
}

__global__ void dinv_kernel() {
    int i = blockIdx.x * blockDim.x + threadIdx.x;
    if (i < N_NODES) g_dinv[i] = rsqrtf(g_deg[i] + 1.0f);
}

// ---------------- weight preprocess: tf32 hi/lo split into mma fragment order
__global__ void wprep_kernel(const float* __restrict__ Wc,
                             const float* __restrict__ Wl) {
    int i = blockIdx.x * blockDim.x + threadIdx.x;
    if (i >= NLAYER * 2 * DIMH * DIMH) return;
    int mat = i / (DIMH * DIMH);
    int rem = i % (DIMH * DIMH);
    int k = rem / DIMH, n = rem % DIMH;
    int layer = mat >> 1, which = mat & 1;
    const float* W = which ? Wl : Wc;
    float w = W[layer * DIMH * DIMH + k * DIMH + n];
    unsigned hb; asm("cvt.rna.tf32.f32 %0, %1;" : "=r"(hb) : "f"(w));
    float hi = __uint_as_float(hb);
    float lof = w - hi;
    unsigned lb; asm("cvt.rna.tf32.f32 %0, %1;" : "=r"(lb) : "f"(lof));
    int kt = k >> 3, nt = n >> 3;
    int lane = (n & 7) * 4 + (k & 3);
    int bi = (k >> 2) & 1;
    float* dst = g_wfrag + (size_t)mat * WFRAG_MAT + ((kt * 16 + nt) * 32 + lane) * 4;
    dst[bi]     = hi;
    dst[2 + bi] = __uint_as_float(lb);
}

// ---------------- tf32 mma helper --------------------------------------------
__device__ __forceinline__ void mma_tf32(float* d, const float4& a,
                                         float b0, float b1) {
    asm volatile(
        "mma.sync.aligned.m16n8k8.row.col.f32.tf32.tf32.f32 "
        "{%0,%1,%2,%3}, {%4,%5,%6,%7}, {%8,%9}, {%0,%1,%2,%3};"
        : "+f"(d[0]), "+f"(d[1]), "+f"(d[2]), "+f"(d[3])
        : "r"(__float_as_uint(a.x)), "r"(__float_as_uint(a.y)),
          "r"(__float_as_uint(a.z)), "r"(__float_as_uint(a.w)),
          "r"(__float_as_uint(b0)),  "r"(__float_as_uint(b1)));
}

// ---------------- fused dual GEMM via 3xTF32 tensor-core mma ------------------
// 64 rows/block, 256 threads (8 warps: warp_m in {0,1} x warp_n in {0..3}).
// A (x) split hi/lo into fragment-ordered smem (2 x 32KB dynamic).
// B (weights) read fragment-ordered from g_wfrag (L2-resident).
// D_conv and D_lin accumulated in two register phases to bound reg pressure.
__global__ __launch_bounds__(256, 2) void gemm_mma_kernel(
    int layer, const float* __restrict__ bcv, const float* __restrict__ blv) {
    extern __shared__ float afrag[];   // hi at 0, lo at +AFRAG_FLOATS
    const int tid  = threadIdx.x;
    const int lane = tid & 31;
    const int wid  = tid >> 5;
    const int warp_m = wid & 1;        // 2 row-halves of 32
    const int warp_n = wid >> 1;       // 4 col-quarters of 32
    const int row0 = blockIdx.x * 64;

    // ---- fill A fragments (hi/lo tf32 split), gmem-coalesced float4 loads ----
#pragma unroll
    for (int it = 0; it < 8; it++) {
        int idx = tid + it * 256;            // 0..2047 over (row 0..63, kvec 0..31)
        int r  = idx >> 5;
        int kv = idx & 31;
        int row = row0 + r;
        float4 v = make_float4(0.f, 0.f, 0.f, 0.f);
        if (row < N_NODES)
            v = __ldg((const float4*)(g_x + (size_t)row * DIMH) + kv);
        int mt = r >> 4, rp = r & 15;
        int lane_base = (rp & 7) * 4;
        int rbit = (rp >> 3) & 1;
        float vv[4] = {v.x, v.y, v.z, v.w};
#pragma unroll
        for (int e = 0; e < 4; e++) {
            int k = kv * 4 + e;
            int kt = k >> 3, c = k & 7;
            int fl = lane_base + (c & 3);
            int slot = rbit + ((c >> 2) << 1);
            unsigned hb; asm("cvt.rna.tf32.f32 %0, %1;" : "=r"(hb) : "f"(vv[e]));
            float hi = __uint_as_float(hb);
            float lof = vv[e] - hi;
            unsigned lb; asm("cvt.rna.tf32.f32 %0, %1;" : "=r"(lb) : "f"(lof));
            int base = ((kt * 4 + mt) * 32 + fl) * 4 + slot;
            afrag[base]                = hi;
            afrag[AFRAG_FLOATS + base] = __uint_as_float(lb);
        }
    }
    __syncthreads();

    const float4* bufC = (const float4*)(g_wfrag + (size_t)(layer * 2 + 0) * WFRAG_MAT);
    const float4* bufL = (const float4*)(g_wfrag + (size_t)(layer * 2 + 1) * WFRAG_MAT);

    float dC[2][4][4];
    float dL[2][4][4];
#pragma unroll
    for (int m = 0; m < 2; m++)
#pragma unroll
        for (int j = 0; j < 4; j++)
#pragma unroll
            for (int q = 0; q < 4; q++) { dC[m][j][q] = 0.f; dL[m][j][q] = 0.f; }

    // ---- phase 1: conv weights ----
#pragma unroll 2
    for (int kt = 0; kt < 16; kt++) {
        float4 ah[2], al[2];
#pragma unroll
        for (int m = 0; m < 2; m++) {
            int o = ((kt * 4 + (warp_m * 2 + m)) * 32 + lane) * 4;
            ah[m] = *(const float4*)&afrag[o];
            al[m] = *(const float4*)&afrag[AFRAG_FLOATS + o];
        }
#pragma unroll
        for (int j = 0; j < 4; j++) {
            int nt = warp_n * 4 + j;
            float4 b = __ldg(bufC + (kt * 16 + nt) * 32 + lane);
#pragma unroll
            for (int m = 0; m < 2; m++) {
                mma_tf32(dC[m][j], ah[m], b.x, b.y);   // hi*hi
                mma_tf32(dC[m][j], ah[m], b.z, b.w);   // hi*lo
                mma_tf32(dC[m][j], al[m], b.x, b.y);   // lo*hi
            }
        }
    }
    // ---- phase 2: lin weights ----
#pragma unroll 2
    for (int kt = 0; kt < 16; kt++) {
        float4 ah[2], al[2];
#pragma unroll
        for (int m = 0; m < 2; m++) {
            int o = ((kt * 4 + (warp_m * 2 + m)) * 32 + lane) * 4;
            ah[m] = *(const float4*)&afrag[o];
            al[m] = *(const float4*)&afrag[AFRAG_FLOATS + o];
        }
#pragma unroll
        for (int j = 0; j < 4; j++) {
            int nt = warp_n * 4 + j;
            float4 b = __ldg(bufL + (kt * 16 + nt) * 32 + lane);
#pragma unroll
            for (int m = 0; m < 2; m++) {
                mma_tf32(dL[m][j], ah[m], b.x, b.y);
                mma_tf32(dL[m][j], ah[m], b.z, b.w);
                mma_tf32(dL[m][j], al[m], b.x, b.y);
            }
        }
    }

    // ---- epilogue: h_scaled = conv*dinv ; acc = h_scaled*dinv + bc + lin + bl
    const int g  = lane >> 2;
    const int tg = lane & 3;
#pragma unroll
    for (int m = 0; m < 2; m++) {
#pragma unroll
        for (int j = 0; j < 4; j++) {
            int colb = warp_n * 32 + j * 8 + tg * 2;
            float bc0 = __ldg(&bcv[colb]),     bc1 = __ldg(&bcv[colb + 1]);
            float bl0 = __ldg(&blv[colb]),     bl1 = __ldg(&blv[colb + 1]);
#pragma unroll
            for (int half = 0; half < 2; half++) {
                int row = row0 + warp_m * 32 + m * 16 + g + half * 8;
                if (row >= N_NODES) continue;
                float dv = g_dinv[row];
                float c0 = dC[m][j][half * 2 + 0], c1 = dC[m][j][half * 2 + 1];
                float l0 = dL[m][j][half * 2 + 0], l1 = dL[m][j][half * 2 + 1];
                float h0 = c0 * dv, h1 = c1 * dv;
                float2 hh = make_float2(h0, h1);
                *(float2*)&g_h[(size_t)row * DIMH + colb] = hh;
                float2 aa = make_float2(fmaf(h0, dv, bc0) + l0 + bl0,
                                        fmaf(h1, dv, bc1) + l1 + bl1);
                *(float2*)&g_acc[(size_t)row * DIMH + colb] = aa;
            }
        }
    }
}

// ---------------- edge scatter: acc[dst] += dinv[dst] * h_scaled[src] --------
__global__ __launch_bounds__(256) void scatter_kernel(const int* __restrict__ ei) {
    int e = blockIdx.x * 8 + (threadIdx.x >> 5);
    int lane = threadIdx.x & 31;
    if (e >= N_EDGES) return;
    int src = __ldg(&ei[e]);
    int dst = __ldg(&ei[N_EDGES + e]);
    float w = __ldg(&g_dinv[dst]);
    float4 v = __ldg((const float4*)(g_h + (size_t)src * DIMH) + lane);
    float* arow = g_acc + (size_t)dst * DIMH + lane * 4;
    asm volatile(
        "red.global.add.v4.f32 [%0], {%1, %2, %3, %4};"
        :: "l"(arow), "f"(v.x * w), "f"(v.y * w), "f"(v.z * w), "f"(v.w * w)
        : "memory");
}

// ---------------- LayerNorm + ReLU + JK accumulate, warp per row -------------
__global__ __launch_bounds__(256) void ln_kernel(const float* __restrict__ gam,
                                                 const float* __restrict__ bet) {
    int row = blockIdx.x * 8 + (threadIdx.x >> 5);
    int lane = threadIdx.x & 31;
    if (row >= N_NODES) return;
    float4 v = ((const float4*)(g_acc + (size_t)row * DIMH))[lane];
    float s  = v.x + v.y + v.z + v.w;
    float sq = v.x * v.x + v.y * v.y + v.z * v.z + v.w * v.w;
#pragma unroll
    for (int o = 16; o; o >>= 1) {
        s  += __shfl_xor_sync(0xFFFFFFFFu, s,  o);
        sq += __shfl_xor_sync(0xFFFFFFFFu, sq, o);
    }
    const float inv128 = 1.0f / 128.0f;
    float mu  = s * inv128;
    float var = sq * inv128 - mu * mu;
    float istd = rsqrtf(var + LN_EPS);
    float4 gg = __ldg((const float4*)gam + lane);
    float4 bb = __ldg((const float4*)bet + lane);
    float4 y;
    y.x = fmaxf((v.x - mu) * istd * gg.x + bb.x, 0.f);
    y.y = fmaxf((v.y - mu) * istd * gg.y + bb.y, 0.f);
    y.z = fmaxf((v.z - mu) * istd * gg.z + bb.z, 0.f);
    y.w = fmaxf((v.w - mu) * istd * gg.w + bb.w, 0.f);
    ((float4*)(g_x + (size_t)row * DIMH))[lane] = y;
    float4 f = ((const float4*)(g_fin + (size_t)row * DIMH))[lane];
    f.x += y.x; f.y += y.y; f.z += y.z; f.w += y.w;
    ((float4*)(g_fin + (size_t)row * DIMH))[lane] = f;
}

// ---------------- prediction head: out = fin @ Wpred + bpred -----------------
__global__ __launch_bounds__(128) void pred_kernel(const float* __restrict__ Wp,
                                                   const float* __restrict__ bp,
                                                   float* __restrict__ out) {
    __shared__ float ws[DIMH * NCLS];
    __shared__ float fs[16][DIMH];
    int tid = threadIdx.x;
    for (int j = tid; j < DIMH * NCLS; j += 128) ws[j] = __ldg(&Wp[j]);
    int row0 = blockIdx.x * 16;
    for (int j = tid; j < 16 * DIMH; j += 128) {
        int r = j >> 7, k = j & 127;
        int row = row0 + r;
        fs[r][k] = (row < N_NODES) ? g_fin[row * DIMH + k] : 0.f;
    }
    __syncthreads();
    for (int idx = tid; idx < 16 * NCLS; idx += 128) {
        int r = idx / NCLS, c = idx % NCLS;
        int row = row0 + r;
        if (row >= N_NODES) continue;
        float acc = __ldg(&bp[c]);
#pragma unroll 8
        for (int k = 0; k < DIMH; k++) acc = fmaf(fs[r][k], ws[k * NCLS + c], acc);
        out[row * NCLS + c] = acc;
    }
}

// ---------------- launch ------------------------------------------------------
extern "C" void kernel_launch(void* const* d_in, const int* in_sizes, int n_in,
                              void* d_out, int out_size) {
    const float* x  = (const float*)d_in[0];
    const int*   ei = (const int*)  d_in[1];
    const float* Wc = (const float*)d_in[2];
    const float* bc = (const float*)d_in[3];
    const float* Wl = (const float*)d_in[4];
    const float* bl = (const float*)d_in[5];
    const float* lg = (const float*)d_in[6];
    const float* lb = (const float*)d_in[7];
    const float* Wp = (const float*)d_in[8];
    const float* bp = (const float*)d_in[9];
    float* out = (float*)d_out;

    const int smem_bytes = 2 * AFRAG_FLOATS * sizeof(float);   // 64 KB
    cudaFuncSetAttribute(gemm_mma_kernel,
                         cudaFuncAttributeMaxDynamicSharedMemorySize, smem_bytes);

    init_kernel<<<(N_NODES * DIMH + 255) / 256, 256>>>(x);
    deg_kernel<<<(N_EDGES + 255) / 256, 256>>>(ei);
    dinv_kernel<<<(N_NODES + 255) / 256, 256>>>();
    wprep_kernel<<<(NLAYER * 2 * DIMH * DIMH + 255) / 256, 256>>>(Wc, Wl);

    for (int i = 0; i < NLAYER; i++) {
        gemm_mma_kernel<<<(N_NODES + 63) / 64, 256, smem_bytes>>>(
            i, bc + i * DIMH, bl + i * DIMH);
        scatter_kernel<<<(N_EDGES + 7) / 8, 256>>>(ei);
        ln_kernel<<<(N_NODES + 7) / 8, 256>>>(lg + i * DIMH, lb + i * DIMH);
    }

    pred_kernel<<<(N_NODES + 15) / 16, 128>>>(Wp, bp, out);
}